// round 14
// baseline (speedup 1.0000x reference)
#include <cuda_runtime.h>
#include <math.h>

// ---------------- problem constants ----------------
#define BT    16          // b*t frames
#define HH    40
#define WW    40
#define CC    128
#define NTOK  (BT*HH*WW)  // 25600
#define MFF   512
#define HEADS 4
#define DH    32
#define KNB   7
#define KK2   49
#define SPA   (8*HH*WW)   // 12800 spatial per batch-b

#define WIN   14          // K/V window side for an 8x8 query tile
#define NWTOK (WIN*WIN)   // 196
#define KSTRIDE 132       // padded row stride (floats): 128 + 4 -> conflict-free
#define ATTN_SMEM ((2*NWTOK*KSTRIDE + 4*13*13) * 4)  // 209,680 bytes

// ---------------- scratch (device globals; no allocations) ----------------
__device__ float g_h   [NTOK*CC];   // running hidden state
__device__ float g_ln  [NTOK*CC];   // layernorm output / staging
__device__ float g_qkv [NTOK*3*CC];
__device__ float g_att [NTOK*CC];
__device__ float g_f1  [NTOK*MFF];
__device__ float g_f2  [NTOK*MFF];

// ---------------- transpose in: x(B=2,C=128,T*H*W=12800) -> h(tok,C) ----------------
__global__ void k_transpose_in(const float* __restrict__ x, float* __restrict__ h)
{
    __shared__ float tile[32][33];
    int b  = blockIdx.z;
    int s0 = blockIdx.x * 32;
    int c0 = blockIdx.y * 32;
    int tx = threadIdx.x, ty = threadIdx.y;
#pragma unroll
    for (int i = 0; i < 32; i += 8)
        tile[ty + i][tx] = x[(size_t)(b*CC + c0 + ty + i) * SPA + s0 + tx];
    __syncthreads();
#pragma unroll
    for (int i = 0; i < 32; i += 8)
        h[(size_t)(b*SPA + s0 + ty + i) * CC + c0 + tx] = tile[tx][ty + i];
}

// ---------------- transpose out: h(tok,C) -> out(B,C,T*H*W) ----------------
__global__ void k_transpose_out(const float* __restrict__ h, float* __restrict__ out)
{
    __shared__ float tile[32][33];
    int b  = blockIdx.z;
    int s0 = blockIdx.x * 32;
    int c0 = blockIdx.y * 32;
    int tx = threadIdx.x, ty = threadIdx.y;
#pragma unroll
    for (int i = 0; i < 32; i += 8)
        tile[ty + i][tx] = h[(size_t)(b*SPA + s0 + ty + i) * CC + c0 + tx];
    __syncthreads();
#pragma unroll
    for (int i = 0; i < 32; i += 8)
        out[(size_t)(b*CC + c0 + ty + i) * SPA + s0 + tx] = tile[tx][ty + i];
}

// ---------------- per-token layernorm over C=128 ----------------
__global__ void k_layernorm(const float* __restrict__ in,
                            const float* __restrict__ g,
                            const float* __restrict__ b,
                            float* __restrict__ out)
{
    int tok = blockIdx.x;
    int c   = threadIdx.x;          // 128 threads
    float v = in[(size_t)tok*CC + c];
    float s = v, q = v*v;
#pragma unroll
    for (int o = 16; o > 0; o >>= 1) {
        s += __shfl_xor_sync(0xffffffffu, s, o);
        q += __shfl_xor_sync(0xffffffffu, q, o);
    }
    __shared__ float sh[8];
    int wid = c >> 5, lane = c & 31;
    if (lane == 0) { sh[wid] = s; sh[4+wid] = q; }
    __syncthreads();
    s = sh[0]+sh[1]+sh[2]+sh[3];
    q = sh[4]+sh[5]+sh[6]+sh[7];
    float mean = s * (1.0f/CC);
    float var  = q * (1.0f/CC) - mean*mean;
    float r    = rsqrtf(var + 1e-5f);
    out[(size_t)tok*CC + c] = (v - mean) * r * g[c] + b[c];
}

// ---------------- SGEMM v2: C[M,N] = A[M,K] @ B[K,N] + bias (+res) ----------------
// BN=128 fixed, BK=16, 256 threads. BM=128 (TM=8) or BM=64 (TM=4), TN=8.
// Double-buffered smem, register-staged prefetch, float4 everywhere.
// Requires: M%BM==0, N%128==0, K%16==0.
template<int BM, int TM, bool RES>
__global__ __launch_bounds__(256)
void k_sgemm2(const float* __restrict__ A, const float* __restrict__ B,
              const float* __restrict__ bias, const float* __restrict__ res,
              float* __restrict__ C, int M, int N, int K)
{
    constexpr int BN = 128;
    constexpr int BK = 16;
    constexpr int TN = 8;
    constexpr int PBM = BM + 4;            // pad keeps rows 16B-aligned (BM%4==0)
    constexpr int NA = BM / 64;            // float4 A-loads per thread (1 or 2)

    __shared__ __align__(16) float As[2][BK][PBM];  // [k][row]
    __shared__ __align__(16) float Bs[2][BK][BN];   // [k][col]

    const int tid = threadIdx.x;
    const int tx  = tid & 15;              // 0..15 -> 8 cols (two float4)
    const int ty  = tid >> 4;              // 0..15 -> TM rows
    const int row0 = blockIdx.y * BM;
    const int col0 = blockIdx.x * BN;

    float4 pa[NA], pb[2];

    // ---- global -> regs ----
    auto loadA = [&](int k0) {
#pragma unroll
        for (int p = 0; p < NA; p++) {
            int id  = tid + p * 256;
            int row = id >> 2;             // 0..BM-1
            int kq  = id & 3;              // 0..3 (float4 along K)
            pa[p] = *(const float4*)&A[(size_t)(row0 + row) * K + k0 + kq * 4];
        }
    };
    auto loadB = [&](int k0) {
#pragma unroll
        for (int p = 0; p < 2; p++) {
            int id = tid + p * 256;
            int kr = id >> 5;              // 0..15
            int cq = id & 31;              // 0..31 -> col = cq*4
            pb[p] = *(const float4*)&B[(size_t)(k0 + kr) * N + col0 + cq * 4];
        }
    };
    // ---- regs -> smem ----
    auto storeA = [&](int buf) {
#pragma unroll
        for (int p = 0; p < NA; p++) {
            int id  = tid + p * 256;
            int row = id >> 2;
            int kq  = id & 3;
            As[buf][kq*4 + 0][row] = pa[p].x;
            As[buf][kq*4 + 1][row] = pa[p].y;
            As[buf][kq*4 + 2][row] = pa[p].z;
            As[buf][kq*4 + 3][row] = pa[p].w;
        }
    };
    auto storeB = [&](int buf) {
#pragma unroll
        for (int p = 0; p < 2; p++) {
            int id = tid + p * 256;
            int kr = id >> 5;
            int cq = id & 31;
            *(float4*)&Bs[buf][kr][cq * 4] = pb[p];
        }
    };

    float acc[TM][TN];
#pragma unroll
    for (int i = 0; i < TM; i++)
#pragma unroll
        for (int j = 0; j < TN; j++) acc[i][j] = 0.0f;

    loadA(0); loadB(0);
    storeA(0); storeB(0);
    __syncthreads();

    const int nk = K / BK;
    int cur = 0;
    for (int t = 0; t < nk; t++) {
        if (t + 1 < nk) { loadA((t + 1) * BK); loadB((t + 1) * BK); }

#pragma unroll
        for (int kk = 0; kk < BK; kk++) {
            float a[TM], b[TN];
            *(float4*)&a[0] = *(const float4*)&As[cur][kk][ty * 4];
            if constexpr (TM == 8)
                *(float4*)&a[4] = *(const float4*)&As[cur][kk][64 + ty * 4];
            *(float4*)&b[0] = *(const float4*)&Bs[cur][kk][tx * 4];
            *(float4*)&b[4] = *(const float4*)&Bs[cur][kk][64 + tx * 4];
#pragma unroll
            for (int i = 0; i < TM; i++)
#pragma unroll
                for (int j = 0; j < TN; j++)
                    acc[i][j] += a[i] * b[j];
        }

        if (t + 1 < nk) {
            storeA(cur ^ 1); storeB(cur ^ 1);
            __syncthreads();
            cur ^= 1;
        }
    }

    // ---- epilogue: bias (+res), float4 stores ----
#pragma unroll
    for (int i = 0; i < TM; i++) {
        int r;
        if constexpr (TM == 8) r = row0 + ((i < 4) ? (ty*4 + i) : (64 + ty*4 + i - 4));
        else                   r = row0 + ty*4 + i;
#pragma unroll
        for (int jq = 0; jq < 2; jq++) {
            int c = col0 + jq*64 + tx*4;
            float4 bv = *(const float4*)&bias[c];
            float4 o;
            o.x = acc[i][jq*4 + 0] + bv.x;
            o.y = acc[i][jq*4 + 1] + bv.y;
            o.z = acc[i][jq*4 + 2] + bv.z;
            o.w = acc[i][jq*4 + 3] + bv.w;
            if (RES) {
                float4 rv = *(const float4*)&res[(size_t)r * N + c];
                o.x += rv.x; o.y += rv.y; o.z += rv.z; o.w += rv.w;
            }
            *(float4*)&C[(size_t)r * N + c] = o;
        }
    }
}

// ---------------- neighborhood attention v2: tiled, shuffle-free ----------------
// Block = 8x8 query tile x 4 heads (256 threads). Stages the 14x14 K/V window
// (all heads) + rpb in dynamic smem; each thread owns one (query, head):
// 49 logits from smem dots, in-register softmax, weighted-V accumulation.
__global__ __launch_bounds__(256)
void k_attn2(const float* __restrict__ qkv,
             const float* __restrict__ rpb,   // [4][13][13] for this layer
             float* __restrict__ out)
{
    extern __shared__ float s[];
    float* Ks   = s;                               // [196][132]
    float* Vs   = s + NWTOK*KSTRIDE;               // [196][132]
    float* srpb = s + 2*NWTOK*KSTRIDE;             // [676]

    const int tid = threadIdx.x;
    const int bt  = blockIdx.z;
    const int ty0 = blockIdx.y * 8;
    const int tx0 = blockIdx.x * 8;
    const int wy0 = min(max(ty0 - 3, 0), HH - WIN);
    const int wx0 = min(max(tx0 - 3, 0), WW - WIN);

    // stage rpb
    for (int i = tid; i < HEADS*13*13; i += 256) srpb[i] = rpb[i];

    // stage K/V window: 196 tokens x 32 float4 each
    for (int idx = tid; idx < NWTOK*32; idx += 256) {
        int r  = idx >> 5;
        int c4 = idx & 31;
        int ry = r / WIN;
        int rx = r - ry * WIN;
        const float* src = qkv + (size_t)((bt*HH + wy0 + ry)*WW + wx0 + rx)*384 + CC + c4*4;
        *(float4*)&Ks[r*KSTRIDE + c4*4] = *(const float4*)src;
        *(float4*)&Vs[r*KSTRIDE + c4*4] = *(const float4*)(src + CC);
    }
    __syncthreads();

    const int q   = tid & 63;
    const int h   = tid >> 6;
    const int qy  = ty0 + (q >> 3);
    const int qx  = tx0 + (q & 7);
    const int tok = (bt*HH + qy)*WW + qx;
    const int sy  = min(max(qy - 3, 0), HH - KNB);
    const int sx  = min(max(qx - 3, 0), WW - KNB);
    const int r0  = (sy - wy0)*WIN + (sx - wx0);
    const int rpb0 = h*169 + (sy - qy + 6)*13 + (sx - qx + 6);

    // q vector (scaled)
    float qv[DH];
#pragma unroll
    for (int d4 = 0; d4 < 8; d4++)
        *(float4*)&qv[d4*4] = *(const float4*)&qkv[(size_t)tok*384 + h*DH + d4*4];
#pragma unroll
    for (int d = 0; d < DH; d++) qv[d] *= 0.17677669529663687f;

    // logits
    float lg[KK2];
#pragma unroll
    for (int i = 0; i < KNB; i++)
#pragma unroll
        for (int j = 0; j < KNB; j++) {
            const float* kr = &Ks[(r0 + i*WIN + j)*KSTRIDE + h*DH];
            float p = 0.0f;
#pragma unroll
            for (int d4 = 0; d4 < 8; d4++) {
                float4 kv4 = *(const float4*)&kr[d4*4];
                p += qv[d4*4+0]*kv4.x + qv[d4*4+1]*kv4.y
                   + qv[d4*4+2]*kv4.z + qv[d4*4+3]*kv4.w;
            }
            lg[i*KNB + j] = p + srpb[rpb0 + i*13 + j];
        }

    // in-register softmax over 49
    float m = lg[0];
#pragma unroll
    for (int i = 1; i < KK2; i++) m = fmaxf(m, lg[i]);
    float ssum = 0.0f;
#pragma unroll
    for (int i = 0; i < KK2; i++) { lg[i] = __expf(lg[i] - m); ssum += lg[i]; }
    const float inv = 1.0f / ssum;

    // weighted V
    float acc[DH];
#pragma unroll
    for (int d = 0; d < DH; d++) acc[d] = 0.0f;
#pragma unroll
    for (int i = 0; i < KNB; i++)
#pragma unroll
        for (int j = 0; j < KNB; j++) {
            const float* vr = &Vs[(r0 + i*WIN + j)*KSTRIDE + h*DH];
            float w = lg[i*KNB + j];
#pragma unroll
            for (int d4 = 0; d4 < 8; d4++) {
                float4 vv4 = *(const float4*)&vr[d4*4];
                acc[d4*4+0] += w*vv4.x; acc[d4*4+1] += w*vv4.y;
                acc[d4*4+2] += w*vv4.z; acc[d4*4+3] += w*vv4.w;
            }
        }

#pragma unroll
    for (int d4 = 0; d4 < 8; d4++) {
        float4 o;
        o.x = acc[d4*4+0]*inv; o.y = acc[d4*4+1]*inv;
        o.z = acc[d4*4+2]*inv; o.w = acc[d4*4+3]*inv;
        *(float4*)&out[(size_t)tok*CC + h*DH + d4*4] = o;
    }
}

// ---------------- depthwise 3x3x3 conv (SAME, over t,y,x) + exact GELU ----------------
__global__ void k_dwconv_gelu(const float* __restrict__ in,
                              const float* __restrict__ w,    // [3][3][3][1][512]
                              const float* __restrict__ bias, // [512]
                              float* __restrict__ out)
{
    int e = blockIdx.x * blockDim.x + threadIdx.x;
    if (e >= NTOK * MFF) return;
    int m   = e & (MFF - 1);
    int tok = e >> 9;
    int x  = tok % WW;
    int y  = (tok / WW) % HH;
    int bt = tok / (HH*WW);
    int b  = bt >> 3;
    int t  = bt & 7;

    float acc = bias[m];
#pragma unroll
    for (int kd = 0; kd < 3; kd++) {
        int tt = t + kd - 1;
        if (tt < 0 || tt > 7) continue;
#pragma unroll
        for (int kh = 0; kh < 3; kh++) {
            int yy = y + kh - 1;
            if (yy < 0 || yy >= HH) continue;
#pragma unroll
            for (int kw = 0; kw < 3; kw++) {
                int xx = x + kw - 1;
                if (xx < 0 || xx >= WW) continue;
                size_t idx = ((size_t)((b*8 + tt)*HH + yy) * WW + xx) * MFF + m;
                acc += in[idx] * w[((kd*3 + kh)*3 + kw) * MFF + m];
            }
        }
    }
    // exact gelu: 0.5*x*(1+erf(x/sqrt(2)))
    out[e] = 0.5f * acc * (1.0f + erff(acc * 0.7071067811865475f));
}

// ---------------- host launcher ----------------
extern "C" void kernel_launch(void* const* d_in, const int* in_sizes, int n_in,
                              void* d_out, int out_size)
{
    const float* x      = (const float*)d_in[0];
    const float* ln1_g  = (const float*)d_in[1];
    const float* ln1_b  = (const float*)d_in[2];
    const float* qkv_w  = (const float*)d_in[3];
    const float* qkv_b  = (const float*)d_in[4];
    const float* rpb    = (const float*)d_in[5];
    const float* proj_w = (const float*)d_in[6];
    const float* proj_b = (const float*)d_in[7];
    const float* ln2_g  = (const float*)d_in[8];
    const float* ln2_b  = (const float*)d_in[9];
    const float* fc1_w  = (const float*)d_in[10];
    const float* fc1_b  = (const float*)d_in[11];
    const float* dw_w   = (const float*)d_in[12];
    const float* dw_b   = (const float*)d_in[13];
    const float* fc2_w  = (const float*)d_in[14];
    const float* fc2_b  = (const float*)d_in[15];
    const float* out_g  = (const float*)d_in[16];
    const float* out_b  = (const float*)d_in[17];
    float* out = (float*)d_out;

    static float *p_h=nullptr,*p_ln,*p_qkv,*p_att,*p_f1,*p_f2;
    if (!p_h) {
        cudaGetSymbolAddress((void**)&p_h,   g_h);
        cudaGetSymbolAddress((void**)&p_ln,  g_ln);
        cudaGetSymbolAddress((void**)&p_qkv, g_qkv);
        cudaGetSymbolAddress((void**)&p_att, g_att);
        cudaGetSymbolAddress((void**)&p_f1,  g_f1);
        cudaGetSymbolAddress((void**)&p_f2,  g_f2);
        cudaFuncSetAttribute(k_attn2, cudaFuncAttributeMaxDynamicSharedMemorySize,
                             ATTN_SMEM);
    }

    dim3 tposeGrid(SPA/32, CC/32, 2);
    dim3 tposeBlk(32, 8);
    dim3 attnGrid(WW/8, HH/8, BT);   // 5 x 5 x 16

    k_transpose_in<<<tposeGrid, tposeBlk>>>(x, p_h);

    for (int l = 0; l < 2; l++) {
        // --- attention sub-block ---
        k_layernorm<<<NTOK, 128>>>(p_h, ln1_g + l*CC, ln1_b + l*CC, p_ln);
        // qkv: [25600,128] @ [128,384]
        k_sgemm2<128, 8, false><<<dim3(384/128, NTOK/128), 256>>>(
            p_ln, qkv_w + (size_t)l*CC*384, qkv_b + l*384, nullptr, p_qkv,
            NTOK, 384, CC);
        k_attn2<<<attnGrid, 256, ATTN_SMEM>>>(p_qkv, rpb + l*HEADS*13*13, p_att);
        // proj: [25600,128] @ [128,128] + residual
        k_sgemm2<64, 4, true><<<dim3(CC/128, NTOK/64), 256>>>(
            p_att, proj_w + (size_t)l*CC*CC, proj_b + l*CC, p_h, p_h,
            NTOK, CC, CC);

        // --- mixffn sub-block ---
        k_layernorm<<<NTOK, 128>>>(p_h, ln2_g + l*CC, ln2_b + l*CC, p_ln);
        // fc1: [25600,128] @ [128,512]
        k_sgemm2<128, 8, false><<<dim3(MFF/128, NTOK/128), 256>>>(
            p_ln, fc1_w + (size_t)l*CC*MFF, fc1_b + l*MFF, nullptr, p_f1,
            NTOK, MFF, CC);
        k_dwconv_gelu<<<(NTOK*MFF + 255)/256, 256>>>(
            p_f1, dw_w + (size_t)l*27*MFF, dw_b + l*MFF, p_f2);
        // fc2: [25600,512] @ [512,128] + residual
        k_sgemm2<64, 4, true><<<dim3(CC/128, NTOK/64), 256>>>(
            p_f2, fc2_w + (size_t)l*MFF*CC, fc2_b + l*CC, p_h, p_h,
            NTOK, CC, MFF);
    }

    k_layernorm<<<NTOK, 128>>>(p_h, out_g, out_b, p_ln);
    k_transpose_out<<<tposeGrid, tposeBlk>>>(p_ln, out);
}

// round 15
// speedup vs baseline: 1.5669x; 1.5669x over previous
#include <cuda_runtime.h>
#include <math.h>

// ---------------- problem constants ----------------
#define BT    16          // b*t frames
#define HH    40
#define WW    40
#define CC    128
#define NTOK  (BT*HH*WW)  // 25600
#define MFF   512
#define HEADS 4
#define DH    32
#define KNB   7
#define KK2   49
#define SPA   (8*HH*WW)   // 12800 spatial per batch-b

#define WIN   14          // K/V window side for an 8x8 query tile
#define NWTOK (WIN*WIN)   // 196
#define KST3  68          // padded row stride (floats) for 64-ch half: conflict-free
#define ATTN3_SMEM ((NWTOK*KST3 + 2*169) * 4)   // 54,664 bytes

// ---------------- scratch (device globals; no allocations) ----------------
__device__ float g_h   [NTOK*CC];   // running hidden state
__device__ float g_ln  [NTOK*CC];   // layernorm output / staging
__device__ float g_qkv [NTOK*3*CC];
__device__ float g_att [NTOK*CC];
__device__ float g_f1  [NTOK*MFF];
__device__ float g_f2  [NTOK*MFF];

// ---------------- transpose in: x(B=2,C=128,T*H*W=12800) -> h(tok,C) ----------------
__global__ void k_transpose_in(const float* __restrict__ x, float* __restrict__ h)
{
    __shared__ float tile[32][33];
    int b  = blockIdx.z;
    int s0 = blockIdx.x * 32;
    int c0 = blockIdx.y * 32;
    int tx = threadIdx.x, ty = threadIdx.y;
#pragma unroll
    for (int i = 0; i < 32; i += 8)
        tile[ty + i][tx] = x[(size_t)(b*CC + c0 + ty + i) * SPA + s0 + tx];
    __syncthreads();
#pragma unroll
    for (int i = 0; i < 32; i += 8)
        h[(size_t)(b*SPA + s0 + ty + i) * CC + c0 + tx] = tile[tx][ty + i];
}

// ---------------- transpose out: h(tok,C) -> out(B,C,T*H*W) ----------------
__global__ void k_transpose_out(const float* __restrict__ h, float* __restrict__ out)
{
    __shared__ float tile[32][33];
    int b  = blockIdx.z;
    int s0 = blockIdx.x * 32;
    int c0 = blockIdx.y * 32;
    int tx = threadIdx.x, ty = threadIdx.y;
#pragma unroll
    for (int i = 0; i < 32; i += 8)
        tile[ty + i][tx] = h[(size_t)(b*SPA + s0 + ty + i) * CC + c0 + tx];
    __syncthreads();
#pragma unroll
    for (int i = 0; i < 32; i += 8)
        out[(size_t)(b*CC + c0 + ty + i) * SPA + s0 + tx] = tile[tx][ty + i];
}

// ---------------- per-token layernorm over C=128 ----------------
__global__ void k_layernorm(const float* __restrict__ in,
                            const float* __restrict__ g,
                            const float* __restrict__ b,
                            float* __restrict__ out)
{
    int tok = blockIdx.x;
    int c   = threadIdx.x;          // 128 threads
    float v = in[(size_t)tok*CC + c];
    float s = v, q = v*v;
#pragma unroll
    for (int o = 16; o > 0; o >>= 1) {
        s += __shfl_xor_sync(0xffffffffu, s, o);
        q += __shfl_xor_sync(0xffffffffu, q, o);
    }
    __shared__ float sh[8];
    int wid = c >> 5, lane = c & 31;
    if (lane == 0) { sh[wid] = s; sh[4+wid] = q; }
    __syncthreads();
    s = sh[0]+sh[1]+sh[2]+sh[3];
    q = sh[4]+sh[5]+sh[6]+sh[7];
    float mean = s * (1.0f/CC);
    float var  = q * (1.0f/CC) - mean*mean;
    float r    = rsqrtf(var + 1e-5f);
    out[(size_t)tok*CC + c] = (v - mean) * r * g[c] + b[c];
}

// ---------------- SGEMM v2: C[M,N] = A[M,K] @ B[K,N] + bias (+res) ----------------
// BN=128 fixed, BK=16, 256 threads. BM=128 (TM=8) or BM=64 (TM=4), TN=8.
// Double-buffered smem, register-staged prefetch, float4 everywhere.
// Requires: M%BM==0, N%128==0, K%16==0.
template<int BM, int TM, bool RES>
__global__ __launch_bounds__(256)
void k_sgemm2(const float* __restrict__ A, const float* __restrict__ B,
              const float* __restrict__ bias, const float* __restrict__ res,
              float* __restrict__ C, int M, int N, int K)
{
    constexpr int BN = 128;
    constexpr int BK = 16;
    constexpr int TN = 8;
    constexpr int PBM = BM + 4;            // pad keeps rows 16B-aligned (BM%4==0)
    constexpr int NA = BM / 64;            // float4 A-loads per thread (1 or 2)

    __shared__ __align__(16) float As[2][BK][PBM];  // [k][row]
    __shared__ __align__(16) float Bs[2][BK][BN];   // [k][col]

    const int tid = threadIdx.x;
    const int tx  = tid & 15;              // 0..15 -> 8 cols (two float4)
    const int ty  = tid >> 4;              // 0..15 -> TM rows
    const int row0 = blockIdx.y * BM;
    const int col0 = blockIdx.x * BN;

    float4 pa[NA], pb[2];

    // ---- global -> regs ----
    auto loadA = [&](int k0) {
#pragma unroll
        for (int p = 0; p < NA; p++) {
            int id  = tid + p * 256;
            int row = id >> 2;             // 0..BM-1
            int kq  = id & 3;              // 0..3 (float4 along K)
            pa[p] = *(const float4*)&A[(size_t)(row0 + row) * K + k0 + kq * 4];
        }
    };
    auto loadB = [&](int k0) {
#pragma unroll
        for (int p = 0; p < 2; p++) {
            int id = tid + p * 256;
            int kr = id >> 5;              // 0..15
            int cq = id & 31;              // 0..31 -> col = cq*4
            pb[p] = *(const float4*)&B[(size_t)(k0 + kr) * N + col0 + cq * 4];
        }
    };
    // ---- regs -> smem ----
    auto storeA = [&](int buf) {
#pragma unroll
        for (int p = 0; p < NA; p++) {
            int id  = tid + p * 256;
            int row = id >> 2;
            int kq  = id & 3;
            As[buf][kq*4 + 0][row] = pa[p].x;
            As[buf][kq*4 + 1][row] = pa[p].y;
            As[buf][kq*4 + 2][row] = pa[p].z;
            As[buf][kq*4 + 3][row] = pa[p].w;
        }
    };
    auto storeB = [&](int buf) {
#pragma unroll
        for (int p = 0; p < 2; p++) {
            int id = tid + p * 256;
            int kr = id >> 5;
            int cq = id & 31;
            *(float4*)&Bs[buf][kr][cq * 4] = pb[p];
        }
    };

    float acc[TM][TN];
#pragma unroll
    for (int i = 0; i < TM; i++)
#pragma unroll
        for (int j = 0; j < TN; j++) acc[i][j] = 0.0f;

    loadA(0); loadB(0);
    storeA(0); storeB(0);
    __syncthreads();

    const int nk = K / BK;
    int cur = 0;
    for (int t = 0; t < nk; t++) {
        if (t + 1 < nk) { loadA((t + 1) * BK); loadB((t + 1) * BK); }

#pragma unroll
        for (int kk = 0; kk < BK; kk++) {
            float a[TM], b[TN];
            *(float4*)&a[0] = *(const float4*)&As[cur][kk][ty * 4];
            if constexpr (TM == 8)
                *(float4*)&a[4] = *(const float4*)&As[cur][kk][64 + ty * 4];
            *(float4*)&b[0] = *(const float4*)&Bs[cur][kk][tx * 4];
            *(float4*)&b[4] = *(const float4*)&Bs[cur][kk][64 + tx * 4];
#pragma unroll
            for (int i = 0; i < TM; i++)
#pragma unroll
                for (int j = 0; j < TN; j++)
                    acc[i][j] += a[i] * b[j];
        }

        if (t + 1 < nk) {
            storeA(cur ^ 1); storeB(cur ^ 1);
            __syncthreads();
            cur ^= 1;
        }
    }

    // ---- epilogue: bias (+res), float4 stores ----
#pragma unroll
    for (int i = 0; i < TM; i++) {
        int r;
        if constexpr (TM == 8) r = row0 + ((i < 4) ? (ty*4 + i) : (64 + ty*4 + i - 4));
        else                   r = row0 + ty*4 + i;
#pragma unroll
        for (int jq = 0; jq < 2; jq++) {
            int c = col0 + jq*64 + tx*4;
            float4 bv = *(const float4*)&bias[c];
            float4 o;
            o.x = acc[i][jq*4 + 0] + bv.x;
            o.y = acc[i][jq*4 + 1] + bv.y;
            o.z = acc[i][jq*4 + 2] + bv.z;
            o.w = acc[i][jq*4 + 3] + bv.w;
            if (RES) {
                float4 rv = *(const float4*)&res[(size_t)r * N + c];
                o.x += rv.x; o.y += rv.y; o.z += rv.z; o.w += rv.w;
            }
            *(float4*)&C[(size_t)r * N + c] = o;
        }
    }
}

// ---------------- neighborhood attention v3: tiled, low-smem, head-pair split ----
// Block = 8x8 query tile x 2 heads (128 threads). Stages the 14x14 K window
// (64 channels for this head-pair) in ~55KB smem, computes logits + in-register
// softmax, then RE-STAGES the same buffer with V and does the weighted sum.
// 4 blocks/SM; carveout stays in the small-smem regime shared with the SGEMMs.
__global__ __launch_bounds__(128, 4)
void k_attn3(const float* __restrict__ qkv,
             const float* __restrict__ rpb,   // [4][13][13] for this layer
             float* __restrict__ out)
{
    extern __shared__ float s[];
    float* buf  = s;                    // [196][68]: K, then V (this head-pair)
    float* srpb = s + NWTOK*KST3;       // [2*169]

    const int tid = threadIdx.x;
    const int bt  = blockIdx.z >> 1;
    const int hp  = blockIdx.z & 1;     // head pair: heads {2hp, 2hp+1}
    const int ty0 = blockIdx.y * 8;
    const int tx0 = blockIdx.x * 8;
    const int wy0 = min(max(ty0 - 3, 0), HH - WIN);
    const int wx0 = min(max(tx0 - 3, 0), WW - WIN);

    // stage rpb for this head pair
    for (int i = tid; i < 2*169; i += 128) srpb[i] = rpb[hp*2*169 + i];

    // stage K window (64 channels): 196 tokens x 16 float4
    for (int idx = tid; idx < NWTOK*16; idx += 128) {
        int r  = idx >> 4;
        int c4 = idx & 15;
        int ry = r / WIN;
        int rx = r - ry * WIN;
        *(float4*)&buf[r*KST3 + c4*4] = *(const float4*)(
            qkv + (size_t)((bt*HH + wy0 + ry)*WW + wx0 + rx)*384 + CC + hp*64 + c4*4);
    }
    __syncthreads();

    const int q    = tid & 63;
    const int h2   = tid >> 6;            // 0..1 within pair
    const int head = hp*2 + h2;
    const int qy   = ty0 + (q >> 3);
    const int qx   = tx0 + (q & 7);
    const int tok  = (bt*HH + qy)*WW + qx;
    const int sy   = min(max(qy - 3, 0), HH - KNB);
    const int sx   = min(max(qx - 3, 0), WW - KNB);
    const int r0   = (sy - wy0)*WIN + (sx - wx0);
    const int rpb0 = h2*169 + (sy - qy + 6)*13 + (sx - qx + 6);

    // q vector (scaled)
    float qv[DH];
#pragma unroll
    for (int d4 = 0; d4 < 8; d4++)
        *(float4*)&qv[d4*4] = *(const float4*)&qkv[(size_t)tok*384 + head*DH + d4*4];
#pragma unroll
    for (int d = 0; d < DH; d++) qv[d] *= 0.17677669529663687f;

    // logits from smem K
    float lg[KK2];
#pragma unroll
    for (int i = 0; i < KNB; i++)
#pragma unroll
        for (int j = 0; j < KNB; j++) {
            const float* kr = &buf[(r0 + i*WIN + j)*KST3 + h2*DH];
            float p = 0.0f;
#pragma unroll
            for (int d4 = 0; d4 < 8; d4++) {
                float4 kv4 = *(const float4*)&kr[d4*4];
                p += qv[d4*4+0]*kv4.x + qv[d4*4+1]*kv4.y
                   + qv[d4*4+2]*kv4.z + qv[d4*4+3]*kv4.w;
            }
            lg[i*KNB + j] = p + srpb[rpb0 + i*13 + j];
        }

    // in-register softmax over 49
    float m = lg[0];
#pragma unroll
    for (int i = 1; i < KK2; i++) m = fmaxf(m, lg[i]);
    float ssum = 0.0f;
#pragma unroll
    for (int i = 0; i < KK2; i++) { lg[i] = __expf(lg[i] - m); ssum += lg[i]; }
    const float inv = 1.0f / ssum;

    // re-stage buffer with V window (same 64 channels)
    __syncthreads();
    for (int idx = tid; idx < NWTOK*16; idx += 128) {
        int r  = idx >> 4;
        int c4 = idx & 15;
        int ry = r / WIN;
        int rx = r - ry * WIN;
        *(float4*)&buf[r*KST3 + c4*4] = *(const float4*)(
            qkv + (size_t)((bt*HH + wy0 + ry)*WW + wx0 + rx)*384 + 2*CC + hp*64 + c4*4);
    }
    __syncthreads();

    // weighted V
    float acc[DH];
#pragma unroll
    for (int d = 0; d < DH; d++) acc[d] = 0.0f;
#pragma unroll
    for (int i = 0; i < KNB; i++)
#pragma unroll
        for (int j = 0; j < KNB; j++) {
            const float* vr = &buf[(r0 + i*WIN + j)*KST3 + h2*DH];
            float w = lg[i*KNB + j];
#pragma unroll
            for (int d4 = 0; d4 < 8; d4++) {
                float4 vv4 = *(const float4*)&vr[d4*4];
                acc[d4*4+0] += w*vv4.x; acc[d4*4+1] += w*vv4.y;
                acc[d4*4+2] += w*vv4.z; acc[d4*4+3] += w*vv4.w;
            }
        }

#pragma unroll
    for (int d4 = 0; d4 < 8; d4++) {
        float4 o;
        o.x = acc[d4*4+0]*inv; o.y = acc[d4*4+1]*inv;
        o.z = acc[d4*4+2]*inv; o.w = acc[d4*4+3]*inv;
        *(float4*)&out[(size_t)tok*CC + head*DH + d4*4] = o;
    }
}

// ---------------- depthwise 3x3x3 conv (SAME, over t,y,x) + exact GELU ----------------
__global__ void k_dwconv_gelu(const float* __restrict__ in,
                              const float* __restrict__ w,    // [3][3][3][1][512]
                              const float* __restrict__ bias, // [512]
                              float* __restrict__ out)
{
    int e = blockIdx.x * blockDim.x + threadIdx.x;
    if (e >= NTOK * MFF) return;
    int m   = e & (MFF - 1);
    int tok = e >> 9;
    int x  = tok % WW;
    int y  = (tok / WW) % HH;
    int bt = tok / (HH*WW);
    int b  = bt >> 3;
    int t  = bt & 7;

    float acc = bias[m];
#pragma unroll
    for (int kd = 0; kd < 3; kd++) {
        int tt = t + kd - 1;
        if (tt < 0 || tt > 7) continue;
#pragma unroll
        for (int kh = 0; kh < 3; kh++) {
            int yy = y + kh - 1;
            if (yy < 0 || yy >= HH) continue;
#pragma unroll
            for (int kw = 0; kw < 3; kw++) {
                int xx = x + kw - 1;
                if (xx < 0 || xx >= WW) continue;
                size_t idx = ((size_t)((b*8 + tt)*HH + yy) * WW + xx) * MFF + m;
                acc += in[idx] * w[((kd*3 + kh)*3 + kw) * MFF + m];
            }
        }
    }
    // exact gelu: 0.5*x*(1+erf(x/sqrt(2)))
    out[e] = 0.5f * acc * (1.0f + erff(acc * 0.7071067811865475f));
}

// ---------------- host launcher ----------------
extern "C" void kernel_launch(void* const* d_in, const int* in_sizes, int n_in,
                              void* d_out, int out_size)
{
    const float* x      = (const float*)d_in[0];
    const float* ln1_g  = (const float*)d_in[1];
    const float* ln1_b  = (const float*)d_in[2];
    const float* qkv_w  = (const float*)d_in[3];
    const float* qkv_b  = (const float*)d_in[4];
    const float* rpb    = (const float*)d_in[5];
    const float* proj_w = (const float*)d_in[6];
    const float* proj_b = (const float*)d_in[7];
    const float* ln2_g  = (const float*)d_in[8];
    const float* ln2_b  = (const float*)d_in[9];
    const float* fc1_w  = (const float*)d_in[10];
    const float* fc1_b  = (const float*)d_in[11];
    const float* dw_w   = (const float*)d_in[12];
    const float* dw_b   = (const float*)d_in[13];
    const float* fc2_w  = (const float*)d_in[14];
    const float* fc2_b  = (const float*)d_in[15];
    const float* out_g  = (const float*)d_in[16];
    const float* out_b  = (const float*)d_in[17];
    float* out = (float*)d_out;

    static float *p_h=nullptr,*p_ln,*p_qkv,*p_att,*p_f1,*p_f2;
    if (!p_h) {
        cudaGetSymbolAddress((void**)&p_h,   g_h);
        cudaGetSymbolAddress((void**)&p_ln,  g_ln);
        cudaGetSymbolAddress((void**)&p_qkv, g_qkv);
        cudaGetSymbolAddress((void**)&p_att, g_att);
        cudaGetSymbolAddress((void**)&p_f1,  g_f1);
        cudaGetSymbolAddress((void**)&p_f2,  g_f2);
        cudaFuncSetAttribute(k_attn3, cudaFuncAttributeMaxDynamicSharedMemorySize,
                             ATTN3_SMEM);
    }

    dim3 tposeGrid(SPA/32, CC/32, 2);
    dim3 tposeBlk(32, 8);
    dim3 attnGrid(WW/8, HH/8, BT*2);   // 5 x 5 x 32 (z packs frame + head-pair)

    k_transpose_in<<<tposeGrid, tposeBlk>>>(x, p_h);

    for (int l = 0; l < 2; l++) {
        // --- attention sub-block ---
        k_layernorm<<<NTOK, 128>>>(p_h, ln1_g + l*CC, ln1_b + l*CC, p_ln);
        // qkv: [25600,128] @ [128,384]
        k_sgemm2<128, 8, false><<<dim3(384/128, NTOK/128), 256>>>(
            p_ln, qkv_w + (size_t)l*CC*384, qkv_b + l*384, nullptr, p_qkv,
            NTOK, 384, CC);
        k_attn3<<<attnGrid, 128, ATTN3_SMEM>>>(p_qkv, rpb + l*HEADS*13*13, p_att);
        // proj: [25600,128] @ [128,128] + residual
        k_sgemm2<64, 4, true><<<dim3(CC/128, NTOK/64), 256>>>(
            p_att, proj_w + (size_t)l*CC*CC, proj_b + l*CC, p_h, p_h,
            NTOK, CC, CC);

        // --- mixffn sub-block ---
        k_layernorm<<<NTOK, 128>>>(p_h, ln2_g + l*CC, ln2_b + l*CC, p_ln);
        // fc1: [25600,128] @ [128,512]
        k_sgemm2<128, 8, false><<<dim3(MFF/128, NTOK/128), 256>>>(
            p_ln, fc1_w + (size_t)l*CC*MFF, fc1_b + l*MFF, nullptr, p_f1,
            NTOK, MFF, CC);
        k_dwconv_gelu<<<(NTOK*MFF + 255)/256, 256>>>(
            p_f1, dw_w + (size_t)l*27*MFF, dw_b + l*MFF, p_f2);
        // fc2: [25600,512] @ [512,128] + residual
        k_sgemm2<64, 4, true><<<dim3(CC/128, NTOK/64), 256>>>(
            p_f2, fc2_w + (size_t)l*MFF*CC, fc2_b + l*CC, p_h, p_h,
            NTOK, CC, MFF);
    }

    k_layernorm<<<NTOK, 128>>>(p_h, out_g, out_b, p_ln);
    k_transpose_out<<<tposeGrid, tposeBlk>>>(p_ln, out);
}

// round 16
// speedup vs baseline: 1.5716x; 1.0030x over previous
#include <cuda_runtime.h>
#include <math.h>

// ---------------- problem constants ----------------
#define BT    16          // b*t frames
#define HH    40
#define WW    40
#define CC    128
#define NTOK  (BT*HH*WW)  // 25600
#define MFF   512
#define HEADS 4
#define DH    32
#define KNB   7
#define KK2   49
#define SPA   (8*HH*WW)   // 12800 spatial per batch-b

#define WIN   14          // K/V window side for an 8x8 query tile
#define NWTOK (WIN*WIN)   // 196
#define KST3  68          // padded row stride (floats) for 64-ch half: conflict-free
#define ATTN3_SMEM ((NWTOK*KST3 + 2*169) * 4)   // 54,664 bytes

// ---------------- scratch (device globals; no allocations) ----------------
__device__ float g_h   [NTOK*CC];   // running hidden state
__device__ float g_ln  [NTOK*CC];   // layernorm output / staging
__device__ float g_qkv [NTOK*3*CC];
__device__ float g_att [NTOK*CC];
__device__ float g_f1  [NTOK*MFF];
__device__ float g_f2  [NTOK*MFF];

// ---------------- transpose in: x(B=2,C=128,T*H*W=12800) -> h(tok,C) ----------------
__global__ void k_transpose_in(const float* __restrict__ x, float* __restrict__ h)
{
    __shared__ float tile[32][33];
    int b  = blockIdx.z;
    int s0 = blockIdx.x * 32;
    int c0 = blockIdx.y * 32;
    int tx = threadIdx.x, ty = threadIdx.y;
#pragma unroll
    for (int i = 0; i < 32; i += 8)
        tile[ty + i][tx] = x[(size_t)(b*CC + c0 + ty + i) * SPA + s0 + tx];
    __syncthreads();
#pragma unroll
    for (int i = 0; i < 32; i += 8)
        h[(size_t)(b*SPA + s0 + ty + i) * CC + c0 + tx] = tile[tx][ty + i];
}

// ---------------- transpose out: h(tok,C) -> out(B,C,T*H*W) ----------------
__global__ void k_transpose_out(const float* __restrict__ h, float* __restrict__ out)
{
    __shared__ float tile[32][33];
    int b  = blockIdx.z;
    int s0 = blockIdx.x * 32;
    int c0 = blockIdx.y * 32;
    int tx = threadIdx.x, ty = threadIdx.y;
#pragma unroll
    for (int i = 0; i < 32; i += 8)
        tile[ty + i][tx] = h[(size_t)(b*SPA + s0 + ty + i) * CC + c0 + tx];
    __syncthreads();
#pragma unroll
    for (int i = 0; i < 32; i += 8)
        out[(size_t)(b*CC + c0 + ty + i) * SPA + s0 + tx] = tile[tx][ty + i];
}

// ---------------- per-token layernorm over C=128 ----------------
__global__ void k_layernorm(const float* __restrict__ in,
                            const float* __restrict__ g,
                            const float* __restrict__ b,
                            float* __restrict__ out)
{
    int tok = blockIdx.x;
    int c   = threadIdx.x;          // 128 threads
    float v = in[(size_t)tok*CC + c];
    float s = v, q = v*v;
#pragma unroll
    for (int o = 16; o > 0; o >>= 1) {
        s += __shfl_xor_sync(0xffffffffu, s, o);
        q += __shfl_xor_sync(0xffffffffu, q, o);
    }
    __shared__ float sh[8];
    int wid = c >> 5, lane = c & 31;
    if (lane == 0) { sh[wid] = s; sh[4+wid] = q; }
    __syncthreads();
    s = sh[0]+sh[1]+sh[2]+sh[3];
    q = sh[4]+sh[5]+sh[6]+sh[7];
    float mean = s * (1.0f/CC);
    float var  = q * (1.0f/CC) - mean*mean;
    float r    = rsqrtf(var + 1e-5f);
    out[(size_t)tok*CC + c] = (v - mean) * r * g[c] + b[c];
}

// ---------------- SGEMM v2: C[M,N] = A[M,K] @ B[K,N] + bias (+res) ----------------
// BN=128 fixed, BK=16, 256 threads. BM=128 (TM=8) or BM=64 (TM=4), TN=8.
// Double-buffered smem, register-staged prefetch, float4 everywhere.
// Requires: M%BM==0, N%128==0, K%16==0.
template<int BM, int TM, bool RES>
__global__ __launch_bounds__(256)
void k_sgemm2(const float* __restrict__ A, const float* __restrict__ B,
              const float* __restrict__ bias, const float* __restrict__ res,
              float* __restrict__ C, int M, int N, int K)
{
    constexpr int BN = 128;
    constexpr int BK = 16;
    constexpr int TN = 8;
    constexpr int PBM = BM + 4;            // pad keeps rows 16B-aligned (BM%4==0)
    constexpr int NA = BM / 64;            // float4 A-loads per thread (1 or 2)

    __shared__ __align__(16) float As[2][BK][PBM];  // [k][row]
    __shared__ __align__(16) float Bs[2][BK][BN];   // [k][col]

    const int tid = threadIdx.x;
    const int tx  = tid & 15;              // 0..15 -> 8 cols (two float4)
    const int ty  = tid >> 4;              // 0..15 -> TM rows
    const int row0 = blockIdx.y * BM;
    const int col0 = blockIdx.x * BN;

    float4 pa[NA], pb[2];

    // ---- global -> regs ----
    auto loadA = [&](int k0) {
#pragma unroll
        for (int p = 0; p < NA; p++) {
            int id  = tid + p * 256;
            int row = id >> 2;             // 0..BM-1
            int kq  = id & 3;              // 0..3 (float4 along K)
            pa[p] = *(const float4*)&A[(size_t)(row0 + row) * K + k0 + kq * 4];
        }
    };
    auto loadB = [&](int k0) {
#pragma unroll
        for (int p = 0; p < 2; p++) {
            int id = tid + p * 256;
            int kr = id >> 5;              // 0..15
            int cq = id & 31;              // 0..31 -> col = cq*4
            pb[p] = *(const float4*)&B[(size_t)(k0 + kr) * N + col0 + cq * 4];
        }
    };
    // ---- regs -> smem ----
    auto storeA = [&](int buf) {
#pragma unroll
        for (int p = 0; p < NA; p++) {
            int id  = tid + p * 256;
            int row = id >> 2;
            int kq  = id & 3;
            As[buf][kq*4 + 0][row] = pa[p].x;
            As[buf][kq*4 + 1][row] = pa[p].y;
            As[buf][kq*4 + 2][row] = pa[p].z;
            As[buf][kq*4 + 3][row] = pa[p].w;
        }
    };
    auto storeB = [&](int buf) {
#pragma unroll
        for (int p = 0; p < 2; p++) {
            int id = tid + p * 256;
            int kr = id >> 5;
            int cq = id & 31;
            *(float4*)&Bs[buf][kr][cq * 4] = pb[p];
        }
    };

    float acc[TM][TN];
#pragma unroll
    for (int i = 0; i < TM; i++)
#pragma unroll
        for (int j = 0; j < TN; j++) acc[i][j] = 0.0f;

    loadA(0); loadB(0);
    storeA(0); storeB(0);
    __syncthreads();

    const int nk = K / BK;
    int cur = 0;
    for (int t = 0; t < nk; t++) {
        if (t + 1 < nk) { loadA((t + 1) * BK); loadB((t + 1) * BK); }

#pragma unroll
        for (int kk = 0; kk < BK; kk++) {
            float a[TM], b[TN];
            *(float4*)&a[0] = *(const float4*)&As[cur][kk][ty * 4];
            if constexpr (TM == 8)
                *(float4*)&a[4] = *(const float4*)&As[cur][kk][64 + ty * 4];
            *(float4*)&b[0] = *(const float4*)&Bs[cur][kk][tx * 4];
            *(float4*)&b[4] = *(const float4*)&Bs[cur][kk][64 + tx * 4];
#pragma unroll
            for (int i = 0; i < TM; i++)
#pragma unroll
                for (int j = 0; j < TN; j++)
                    acc[i][j] += a[i] * b[j];
        }

        if (t + 1 < nk) {
            storeA(cur ^ 1); storeB(cur ^ 1);
            __syncthreads();
            cur ^= 1;
        }
    }

    // ---- epilogue: bias (+res), float4 stores ----
#pragma unroll
    for (int i = 0; i < TM; i++) {
        int r;
        if constexpr (TM == 8) r = row0 + ((i < 4) ? (ty*4 + i) : (64 + ty*4 + i - 4));
        else                   r = row0 + ty*4 + i;
#pragma unroll
        for (int jq = 0; jq < 2; jq++) {
            int c = col0 + jq*64 + tx*4;
            float4 bv = *(const float4*)&bias[c];
            float4 o;
            o.x = acc[i][jq*4 + 0] + bv.x;
            o.y = acc[i][jq*4 + 1] + bv.y;
            o.z = acc[i][jq*4 + 2] + bv.z;
            o.w = acc[i][jq*4 + 3] + bv.w;
            if (RES) {
                float4 rv = *(const float4*)&res[(size_t)r * N + c];
                o.x += rv.x; o.y += rv.y; o.z += rv.z; o.w += rv.w;
            }
            *(float4*)&C[(size_t)r * N + c] = o;
        }
    }
}

// ---------------- neighborhood attention v3: tiled, low-smem, head-pair split ----
// Block = 8x8 query tile x 2 heads (128 threads). Stages the 14x14 K window
// (64 channels for this head-pair) in ~55KB smem, computes logits + in-register
// softmax, then RE-STAGES the same buffer with V and does the weighted sum.
// 4 blocks/SM; carveout stays in the small-smem regime shared with the SGEMMs.
__global__ __launch_bounds__(128, 4)
void k_attn3(const float* __restrict__ qkv,
             const float* __restrict__ rpb,   // [4][13][13] for this layer
             float* __restrict__ out)
{
    extern __shared__ float s[];
    float* buf  = s;                    // [196][68]: K, then V (this head-pair)
    float* srpb = s + NWTOK*KST3;       // [2*169]

    const int tid = threadIdx.x;
    const int bt  = blockIdx.z >> 1;
    const int hp  = blockIdx.z & 1;     // head pair: heads {2hp, 2hp+1}
    const int ty0 = blockIdx.y * 8;
    const int tx0 = blockIdx.x * 8;
    const int wy0 = min(max(ty0 - 3, 0), HH - WIN);
    const int wx0 = min(max(tx0 - 3, 0), WW - WIN);

    // stage rpb for this head pair
    for (int i = tid; i < 2*169; i += 128) srpb[i] = rpb[hp*2*169 + i];

    // stage K window (64 channels): 196 tokens x 16 float4
    for (int idx = tid; idx < NWTOK*16; idx += 128) {
        int r  = idx >> 4;
        int c4 = idx & 15;
        int ry = r / WIN;
        int rx = r - ry * WIN;
        *(float4*)&buf[r*KST3 + c4*4] = *(const float4*)(
            qkv + (size_t)((bt*HH + wy0 + ry)*WW + wx0 + rx)*384 + CC + hp*64 + c4*4);
    }
    __syncthreads();

    const int q    = tid & 63;
    const int h2   = tid >> 6;            // 0..1 within pair
    const int head = hp*2 + h2;
    const int qy   = ty0 + (q >> 3);
    const int qx   = tx0 + (q & 7);
    const int tok  = (bt*HH + qy)*WW + qx;
    const int sy   = min(max(qy - 3, 0), HH - KNB);
    const int sx   = min(max(qx - 3, 0), WW - KNB);
    const int r0   = (sy - wy0)*WIN + (sx - wx0);
    const int rpb0 = h2*169 + (sy - qy + 6)*13 + (sx - qx + 6);

    // q vector (scaled)
    float qv[DH];
#pragma unroll
    for (int d4 = 0; d4 < 8; d4++)
        *(float4*)&qv[d4*4] = *(const float4*)&qkv[(size_t)tok*384 + head*DH + d4*4];
#pragma unroll
    for (int d = 0; d < DH; d++) qv[d] *= 0.17677669529663687f;

    // logits from smem K
    float lg[KK2];
#pragma unroll
    for (int i = 0; i < KNB; i++)
#pragma unroll
        for (int j = 0; j < KNB; j++) {
            const float* kr = &buf[(r0 + i*WIN + j)*KST3 + h2*DH];
            float p = 0.0f;
#pragma unroll
            for (int d4 = 0; d4 < 8; d4++) {
                float4 kv4 = *(const float4*)&kr[d4*4];
                p += qv[d4*4+0]*kv4.x + qv[d4*4+1]*kv4.y
                   + qv[d4*4+2]*kv4.z + qv[d4*4+3]*kv4.w;
            }
            lg[i*KNB + j] = p + srpb[rpb0 + i*13 + j];
        }

    // in-register softmax over 49
    float m = lg[0];
#pragma unroll
    for (int i = 1; i < KK2; i++) m = fmaxf(m, lg[i]);
    float ssum = 0.0f;
#pragma unroll
    for (int i = 0; i < KK2; i++) { lg[i] = __expf(lg[i] - m); ssum += lg[i]; }
    const float inv = 1.0f / ssum;

    // re-stage buffer with V window (same 64 channels)
    __syncthreads();
    for (int idx = tid; idx < NWTOK*16; idx += 128) {
        int r  = idx >> 4;
        int c4 = idx & 15;
        int ry = r / WIN;
        int rx = r - ry * WIN;
        *(float4*)&buf[r*KST3 + c4*4] = *(const float4*)(
            qkv + (size_t)((bt*HH + wy0 + ry)*WW + wx0 + rx)*384 + 2*CC + hp*64 + c4*4);
    }
    __syncthreads();

    // weighted V
    float acc[DH];
#pragma unroll
    for (int d = 0; d < DH; d++) acc[d] = 0.0f;
#pragma unroll
    for (int i = 0; i < KNB; i++)
#pragma unroll
        for (int j = 0; j < KNB; j++) {
            const float* vr = &buf[(r0 + i*WIN + j)*KST3 + h2*DH];
            float w = lg[i*KNB + j];
#pragma unroll
            for (int d4 = 0; d4 < 8; d4++) {
                float4 vv4 = *(const float4*)&vr[d4*4];
                acc[d4*4+0] += w*vv4.x; acc[d4*4+1] += w*vv4.y;
                acc[d4*4+2] += w*vv4.z; acc[d4*4+3] += w*vv4.w;
            }
        }

#pragma unroll
    for (int d4 = 0; d4 < 8; d4++) {
        float4 o;
        o.x = acc[d4*4+0]*inv; o.y = acc[d4*4+1]*inv;
        o.z = acc[d4*4+2]*inv; o.w = acc[d4*4+3]*inv;
        *(float4*)&out[(size_t)tok*CC + head*DH + d4*4] = o;
    }
}

// ---------------- depthwise 3x3x3 conv (SAME, over t,y,x) + exact GELU ----------------
__global__ void k_dwconv_gelu(const float* __restrict__ in,
                              const float* __restrict__ w,    // [3][3][3][1][512]
                              const float* __restrict__ bias, // [512]
                              float* __restrict__ out)
{
    int e = blockIdx.x * blockDim.x + threadIdx.x;
    if (e >= NTOK * MFF) return;
    int m   = e & (MFF - 1);
    int tok = e >> 9;
    int x  = tok % WW;
    int y  = (tok / WW) % HH;
    int bt = tok / (HH*WW);
    int b  = bt >> 3;
    int t  = bt & 7;

    float acc = bias[m];
#pragma unroll
    for (int kd = 0; kd < 3; kd++) {
        int tt = t + kd - 1;
        if (tt < 0 || tt > 7) continue;
#pragma unroll
        for (int kh = 0; kh < 3; kh++) {
            int yy = y + kh - 1;
            if (yy < 0 || yy >= HH) continue;
#pragma unroll
            for (int kw = 0; kw < 3; kw++) {
                int xx = x + kw - 1;
                if (xx < 0 || xx >= WW) continue;
                size_t idx = ((size_t)((b*8 + tt)*HH + yy) * WW + xx) * MFF + m;
                acc += in[idx] * w[((kd*3 + kh)*3 + kw) * MFF + m];
            }
        }
    }
    // exact gelu: 0.5*x*(1+erf(x/sqrt(2)))
    out[e] = 0.5f * acc * (1.0f + erff(acc * 0.7071067811865475f));
}

// ---------------- host launcher ----------------
extern "C" void kernel_launch(void* const* d_in, const int* in_sizes, int n_in,
                              void* d_out, int out_size)
{
    const float* x      = (const float*)d_in[0];
    const float* ln1_g  = (const float*)d_in[1];
    const float* ln1_b  = (const float*)d_in[2];
    const float* qkv_w  = (const float*)d_in[3];
    const float* qkv_b  = (const float*)d_in[4];
    const float* rpb    = (const float*)d_in[5];
    const float* proj_w = (const float*)d_in[6];
    const float* proj_b = (const float*)d_in[7];
    const float* ln2_g  = (const float*)d_in[8];
    const float* ln2_b  = (const float*)d_in[9];
    const float* fc1_w  = (const float*)d_in[10];
    const float* fc1_b  = (const float*)d_in[11];
    const float* dw_w   = (const float*)d_in[12];
    const float* dw_b   = (const float*)d_in[13];
    const float* fc2_w  = (const float*)d_in[14];
    const float* fc2_b  = (const float*)d_in[15];
    const float* out_g  = (const float*)d_in[16];
    const float* out_b  = (const float*)d_in[17];
    float* out = (float*)d_out;

    static float *p_h=nullptr,*p_ln,*p_qkv,*p_att,*p_f1,*p_f2;
    if (!p_h) {
        cudaGetSymbolAddress((void**)&p_h,   g_h);
        cudaGetSymbolAddress((void**)&p_ln,  g_ln);
        cudaGetSymbolAddress((void**)&p_qkv, g_qkv);
        cudaGetSymbolAddress((void**)&p_att, g_att);
        cudaGetSymbolAddress((void**)&p_f1,  g_f1);
        cudaGetSymbolAddress((void**)&p_f2,  g_f2);
        cudaFuncSetAttribute(k_attn3, cudaFuncAttributeMaxDynamicSharedMemorySize,
                             ATTN3_SMEM);
    }

    dim3 tposeGrid(SPA/32, CC/32, 2);
    dim3 tposeBlk(32, 8);
    dim3 attnGrid(WW/8, HH/8, BT*2);   // 5 x 5 x 32 (z packs frame + head-pair)

    k_transpose_in<<<tposeGrid, tposeBlk>>>(x, p_h);

    for (int l = 0; l < 2; l++) {
        // --- attention sub-block ---
        k_layernorm<<<NTOK, 128>>>(p_h, ln1_g + l*CC, ln1_b + l*CC, p_ln);
        // qkv: [25600,128] @ [128,384]
        k_sgemm2<128, 8, false><<<dim3(384/128, NTOK/128), 256>>>(
            p_ln, qkv_w + (size_t)l*CC*384, qkv_b + l*384, nullptr, p_qkv,
            NTOK, 384, CC);
        k_attn3<<<attnGrid, 128, ATTN3_SMEM>>>(p_qkv, rpb + l*HEADS*13*13, p_att);
        // proj: [25600,128] @ [128,128] + residual
        k_sgemm2<64, 4, true><<<dim3(CC/128, NTOK/64), 256>>>(
            p_att, proj_w + (size_t)l*CC*CC, proj_b + l*CC, p_h, p_h,
            NTOK, CC, CC);

        // --- mixffn sub-block ---
        k_layernorm<<<NTOK, 128>>>(p_h, ln2_g + l*CC, ln2_b + l*CC, p_ln);
        // fc1: [25600,128] @ [128,512]
        k_sgemm2<128, 8, false><<<dim3(MFF/128, NTOK/128), 256>>>(
            p_ln, fc1_w + (size_t)l*CC*MFF, fc1_b + l*MFF, nullptr, p_f1,
            NTOK, MFF, CC);
        k_dwconv_gelu<<<(NTOK*MFF + 255)/256, 256>>>(
            p_f1, dw_w + (size_t)l*27*MFF, dw_b + l*MFF, p_f2);
        // fc2: [25600,512] @ [512,128] + residual
        k_sgemm2<64, 4, true><<<dim3(CC/128, NTOK/64), 256>>>(
            p_f2, fc2_w + (size_t)l*MFF*CC, fc2_b + l*CC, p_h, p_h,
            NTOK, CC, MFF);
    }

    k_layernorm<<<NTOK, 128>>>(p_h, out_g, out_b, p_ln);
    k_transpose_out<<<tposeGrid, tposeBlk>>>(p_ln, out);
}

// round 17
// speedup vs baseline: 2.2781x; 1.4495x over previous
#include <cuda_runtime.h>
#include <math.h>
#include <stdint.h>

// ---------------- problem constants ----------------
#define BT    16          // b*t frames
#define HH    40
#define WW    40
#define CC    128
#define NTOK  (BT*HH*WW)  // 25600
#define MFF   512
#define HEADS 4
#define DH    32
#define KNB   7
#define KK2   49
#define SPA   (8*HH*WW)   // 12800 spatial per batch-b

#define WIN   14          // K/V window side for an 8x8 query tile
#define NWTOK (WIN*WIN)   // 196
#define KST3  68          // padded row stride (floats) for 64-ch half: conflict-free
#define ATTN3_SMEM ((NWTOK*KST3 + 2*169) * 4)   // 54,664 bytes

// ---------------- scratch (device globals; no allocations) ----------------
__device__ float g_h   [NTOK*CC];   // running hidden state
__device__ float g_ln  [NTOK*CC];   // layernorm output / staging
__device__ float g_qkv [NTOK*3*CC];
__device__ float g_att [NTOK*CC];
__device__ float g_f1  [NTOK*MFF];
__device__ float g_f2  [NTOK*MFF];

// ---------------- transpose in: x(B=2,C=128,T*H*W=12800) -> h(tok,C) ----------------
__global__ void k_transpose_in(const float* __restrict__ x, float* __restrict__ h)
{
    __shared__ float tile[32][33];
    int b  = blockIdx.z;
    int s0 = blockIdx.x * 32;
    int c0 = blockIdx.y * 32;
    int tx = threadIdx.x, ty = threadIdx.y;
#pragma unroll
    for (int i = 0; i < 32; i += 8)
        tile[ty + i][tx] = x[(size_t)(b*CC + c0 + ty + i) * SPA + s0 + tx];
    __syncthreads();
#pragma unroll
    for (int i = 0; i < 32; i += 8)
        h[(size_t)(b*SPA + s0 + ty + i) * CC + c0 + tx] = tile[tx][ty + i];
}

// ---------------- transpose out: h(tok,C) -> out(B,C,T*H*W) ----------------
__global__ void k_transpose_out(const float* __restrict__ h, float* __restrict__ out)
{
    __shared__ float tile[32][33];
    int b  = blockIdx.z;
    int s0 = blockIdx.x * 32;
    int c0 = blockIdx.y * 32;
    int tx = threadIdx.x, ty = threadIdx.y;
#pragma unroll
    for (int i = 0; i < 32; i += 8)
        tile[ty + i][tx] = h[(size_t)(b*SPA + s0 + ty + i) * CC + c0 + tx];
    __syncthreads();
#pragma unroll
    for (int i = 0; i < 32; i += 8)
        out[(size_t)(b*CC + c0 + ty + i) * SPA + s0 + tx] = tile[tx][ty + i];
}

// ---------------- per-token layernorm over C=128 ----------------
__global__ void k_layernorm(const float* __restrict__ in,
                            const float* __restrict__ g,
                            const float* __restrict__ b,
                            float* __restrict__ out)
{
    int tok = blockIdx.x;
    int c   = threadIdx.x;          // 128 threads
    float v = in[(size_t)tok*CC + c];
    float s = v, q = v*v;
#pragma unroll
    for (int o = 16; o > 0; o >>= 1) {
        s += __shfl_xor_sync(0xffffffffu, s, o);
        q += __shfl_xor_sync(0xffffffffu, q, o);
    }
    __shared__ float sh[8];
    int wid = c >> 5, lane = c & 31;
    if (lane == 0) { sh[wid] = s; sh[4+wid] = q; }
    __syncthreads();
    s = sh[0]+sh[1]+sh[2]+sh[3];
    q = sh[4]+sh[5]+sh[6]+sh[7];
    float mean = s * (1.0f/CC);
    float var  = q * (1.0f/CC) - mean*mean;
    float r    = rsqrtf(var + 1e-5f);
    out[(size_t)tok*CC + c] = (v - mean) * r * g[c] + b[c];
}

// ---------------- tf32 helpers ----------------
__device__ __forceinline__ float tf32r(float x) {
    uint32_t u;
    asm("cvt.rna.tf32.f32 %0, %1;" : "=r"(u) : "f"(x));
    return __uint_as_float(u);
}

__device__ __forceinline__ void mma_tf32(float* c, const uint32_t* a, const uint32_t* b) {
    asm volatile(
        "mma.sync.aligned.m16n8k8.row.col.f32.tf32.tf32.f32 "
        "{%0,%1,%2,%3}, {%4,%5,%6,%7}, {%8,%9}, {%0,%1,%2,%3};"
        : "+f"(c[0]), "+f"(c[1]), "+f"(c[2]), "+f"(c[3])
        : "r"(a[0]), "r"(a[1]), "r"(a[2]), "r"(a[3]), "r"(b[0]), "r"(b[1]));
}

// ---------------- tf32 tensor-core GEMM: C = A[M,K] @ B[K,N] + bias (+res) ----
// Block tile 128x128, BK=16 double-buffered, 8 warps (2x4), warp tile 64x32
// = 4x4 m16n8k8 fragments. A smem [m][20] and B smem [k][136]: both layouts
// verified bank-conflict-free for the mma fragment gather pattern.
// Requires M%128==0, N%128==0, K%16==0.
template<bool RES>
__global__ __launch_bounds__(256, 2)
void k_tgemm(const float* __restrict__ A, const float* __restrict__ B,
             const float* __restrict__ bias, const float* __restrict__ res,
             float* __restrict__ C, int M, int N, int K)
{
    constexpr int BM = 128, BN = 128, BK = 16;
    constexpr int AST = 20;    // A row stride (floats)
    constexpr int BST = 136;   // B row stride (floats)

    __shared__ __align__(16) float As[2][BM][AST];
    __shared__ __align__(16) float Bs[2][BK][BST];

    const int tid  = threadIdx.x;
    const int lane = tid & 31;
    const int w    = tid >> 5;
    const int wm   = w >> 2;          // 0..1
    const int wn   = w & 3;           // 0..3
    const int gr   = lane >> 2;       // 0..7
    const int gc   = lane & 3;        // 0..3
    const int row0 = blockIdx.y * BM;
    const int col0 = blockIdx.x * BN;

    float4 pa[2], pb[2];

    auto loadA = [&](int k0) {
#pragma unroll
        for (int p = 0; p < 2; p++) {
            int id = tid + p * 256;
            int r  = id >> 2;          // 0..127
            int kq = id & 3;           // float4 along K
            pa[p] = *(const float4*)&A[(size_t)(row0 + r) * K + k0 + kq * 4];
        }
    };
    auto loadB = [&](int k0) {
#pragma unroll
        for (int p = 0; p < 2; p++) {
            int id = tid + p * 256;
            int kr = id >> 5;          // 0..15
            int cq = id & 31;          // float4 along N
            pb[p] = *(const float4*)&B[(size_t)(k0 + kr) * N + col0 + cq * 4];
        }
    };
    auto storeA = [&](int buf) {
#pragma unroll
        for (int p = 0; p < 2; p++) {
            int id = tid + p * 256;
            int r  = id >> 2;
            int kq = id & 3;
            float4 v = pa[p];
            v.x = tf32r(v.x); v.y = tf32r(v.y); v.z = tf32r(v.z); v.w = tf32r(v.w);
            *(float4*)&As[buf][r][kq * 4] = v;
        }
    };
    auto storeB = [&](int buf) {
#pragma unroll
        for (int p = 0; p < 2; p++) {
            int id = tid + p * 256;
            int kr = id >> 5;
            int cq = id & 31;
            float4 v = pb[p];
            v.x = tf32r(v.x); v.y = tf32r(v.y); v.z = tf32r(v.z); v.w = tf32r(v.w);
            *(float4*)&Bs[buf][kr][cq * 4] = v;
        }
    };

    float acc[4][4][4];
#pragma unroll
    for (int i = 0; i < 4; i++)
#pragma unroll
        for (int j = 0; j < 4; j++)
#pragma unroll
            for (int e = 0; e < 4; e++) acc[i][j][e] = 0.0f;

    loadA(0); loadB(0);
    storeA(0); storeB(0);
    __syncthreads();

    const int nk = K / BK;
    int cur = 0;
    for (int t = 0; t < nk; t++) {
        if (t + 1 < nk) { loadA((t + 1) * BK); loadB((t + 1) * BK); }

#pragma unroll
        for (int k8 = 0; k8 < BK; k8 += 8) {
            uint32_t a[4][4], b[4][2];
#pragma unroll
            for (int i = 0; i < 4; i++) {
                const float* p = &As[cur][wm*64 + i*16][k8 + gc];
                a[i][0] = __float_as_uint(p[gr * AST]);
                a[i][1] = __float_as_uint(p[(gr + 8) * AST]);
                a[i][2] = __float_as_uint(p[gr * AST + 4]);
                a[i][3] = __float_as_uint(p[(gr + 8) * AST + 4]);
            }
#pragma unroll
            for (int j = 0; j < 4; j++) {
                const float* p = &Bs[cur][k8 + gc][wn*32 + j*8 + gr];
                b[j][0] = __float_as_uint(p[0]);
                b[j][1] = __float_as_uint(p[4 * BST]);
            }
#pragma unroll
            for (int i = 0; i < 4; i++)
#pragma unroll
                for (int j = 0; j < 4; j++)
                    mma_tf32(acc[i][j], a[i], b[j]);
        }

        if (t + 1 < nk) {
            storeA(cur ^ 1); storeB(cur ^ 1);
            __syncthreads();
            cur ^= 1;
        }
    }

    // ---- epilogue: bias (+res), float2 stores per fragment ----
#pragma unroll
    for (int i = 0; i < 4; i++) {
#pragma unroll
        for (int j = 0; j < 4; j++) {
            int r  = row0 + wm*64 + i*16 + gr;
            int cl = col0 + wn*32 + j*8 + gc*2;
            float2 bv = *(const float2*)&bias[cl];
            float2 o0, o1;
            o0.x = acc[i][j][0] + bv.x;  o0.y = acc[i][j][1] + bv.y;
            o1.x = acc[i][j][2] + bv.x;  o1.y = acc[i][j][3] + bv.y;
            if (RES) {
                float2 r0 = *(const float2*)&res[(size_t)r * N + cl];
                float2 r1 = *(const float2*)&res[(size_t)(r + 8) * N + cl];
                o0.x += r0.x; o0.y += r0.y;
                o1.x += r1.x; o1.y += r1.y;
            }
            *(float2*)&C[(size_t)r * N + cl]       = o0;
            *(float2*)&C[(size_t)(r + 8) * N + cl] = o1;
        }
    }
}

// ---------------- neighborhood attention v3: tiled, low-smem, head-pair split ----
__global__ __launch_bounds__(128, 4)
void k_attn3(const float* __restrict__ qkv,
             const float* __restrict__ rpb,   // [4][13][13] for this layer
             float* __restrict__ out)
{
    extern __shared__ float s[];
    float* buf  = s;                    // [196][68]: K, then V (this head-pair)
    float* srpb = s + NWTOK*KST3;       // [2*169]

    const int tid = threadIdx.x;
    const int bt  = blockIdx.z >> 1;
    const int hp  = blockIdx.z & 1;     // head pair: heads {2hp, 2hp+1}
    const int ty0 = blockIdx.y * 8;
    const int tx0 = blockIdx.x * 8;
    const int wy0 = min(max(ty0 - 3, 0), HH - WIN);
    const int wx0 = min(max(tx0 - 3, 0), WW - WIN);

    // stage rpb for this head pair
    for (int i = tid; i < 2*169; i += 128) srpb[i] = rpb[hp*2*169 + i];

    // stage K window (64 channels): 196 tokens x 16 float4
    for (int idx = tid; idx < NWTOK*16; idx += 128) {
        int r  = idx >> 4;
        int c4 = idx & 15;
        int ry = r / WIN;
        int rx = r - ry * WIN;
        *(float4*)&buf[r*KST3 + c4*4] = *(const float4*)(
            qkv + (size_t)((bt*HH + wy0 + ry)*WW + wx0 + rx)*384 + CC + hp*64 + c4*4);
    }
    __syncthreads();

    const int q    = tid & 63;
    const int h2   = tid >> 6;            // 0..1 within pair
    const int head = hp*2 + h2;
    const int qy   = ty0 + (q >> 3);
    const int qx   = tx0 + (q & 7);
    const int tok  = (bt*HH + qy)*WW + qx;
    const int sy   = min(max(qy - 3, 0), HH - KNB);
    const int sx   = min(max(qx - 3, 0), WW - KNB);
    const int r0   = (sy - wy0)*WIN + (sx - wx0);
    const int rpb0 = h2*169 + (sy - qy + 6)*13 + (sx - qx + 6);

    // q vector (scaled)
    float qv[DH];
#pragma unroll
    for (int d4 = 0; d4 < 8; d4++)
        *(float4*)&qv[d4*4] = *(const float4*)&qkv[(size_t)tok*384 + head*DH + d4*4];
#pragma unroll
    for (int d = 0; d < DH; d++) qv[d] *= 0.17677669529663687f;

    // logits from smem K
    float lg[KK2];
#pragma unroll
    for (int i = 0; i < KNB; i++)
#pragma unroll
        for (int j = 0; j < KNB; j++) {
            const float* kr = &buf[(r0 + i*WIN + j)*KST3 + h2*DH];
            float p = 0.0f;
#pragma unroll
            for (int d4 = 0; d4 < 8; d4++) {
                float4 kv4 = *(const float4*)&kr[d4*4];
                p += qv[d4*4+0]*kv4.x + qv[d4*4+1]*kv4.y
                   + qv[d4*4+2]*kv4.z + qv[d4*4+3]*kv4.w;
            }
            lg[i*KNB + j] = p + srpb[rpb0 + i*13 + j];
        }

    // in-register softmax over 49
    float m = lg[0];
#pragma unroll
    for (int i = 1; i < KK2; i++) m = fmaxf(m, lg[i]);
    float ssum = 0.0f;
#pragma unroll
    for (int i = 0; i < KK2; i++) { lg[i] = __expf(lg[i] - m); ssum += lg[i]; }
    const float inv = 1.0f / ssum;

    // re-stage buffer with V window (same 64 channels)
    __syncthreads();
    for (int idx = tid; idx < NWTOK*16; idx += 128) {
        int r  = idx >> 4;
        int c4 = idx & 15;
        int ry = r / WIN;
        int rx = r - ry * WIN;
        *(float4*)&buf[r*KST3 + c4*4] = *(const float4*)(
            qkv + (size_t)((bt*HH + wy0 + ry)*WW + wx0 + rx)*384 + 2*CC + hp*64 + c4*4);
    }
    __syncthreads();

    // weighted V
    float acc[DH];
#pragma unroll
    for (int d = 0; d < DH; d++) acc[d] = 0.0f;
#pragma unroll
    for (int i = 0; i < KNB; i++)
#pragma unroll
        for (int j = 0; j < KNB; j++) {
            const float* vr = &buf[(r0 + i*WIN + j)*KST3 + h2*DH];
            float w = lg[i*KNB + j];
#pragma unroll
            for (int d4 = 0; d4 < 8; d4++) {
                float4 vv4 = *(const float4*)&vr[d4*4];
                acc[d4*4+0] += w*vv4.x; acc[d4*4+1] += w*vv4.y;
                acc[d4*4+2] += w*vv4.z; acc[d4*4+3] += w*vv4.w;
            }
        }

#pragma unroll
    for (int d4 = 0; d4 < 8; d4++) {
        float4 o;
        o.x = acc[d4*4+0]*inv; o.y = acc[d4*4+1]*inv;
        o.z = acc[d4*4+2]*inv; o.w = acc[d4*4+3]*inv;
        *(float4*)&out[(size_t)tok*CC + head*DH + d4*4] = o;
    }
}

// ---------------- depthwise 3x3x3 conv (SAME, over t,y,x) + exact GELU ----------------
__global__ void k_dwconv_gelu(const float* __restrict__ in,
                              const float* __restrict__ w,    // [3][3][3][1][512]
                              const float* __restrict__ bias, // [512]
                              float* __restrict__ out)
{
    int e = blockIdx.x * blockDim.x + threadIdx.x;
    if (e >= NTOK * MFF) return;
    int m   = e & (MFF - 1);
    int tok = e >> 9;
    int x  = tok % WW;
    int y  = (tok / WW) % HH;
    int bt = tok / (HH*WW);
    int b  = bt >> 3;
    int t  = bt & 7;

    float acc = bias[m];
#pragma unroll
    for (int kd = 0; kd < 3; kd++) {
        int tt = t + kd - 1;
        if (tt < 0 || tt > 7) continue;
#pragma unroll
        for (int kh = 0; kh < 3; kh++) {
            int yy = y + kh - 1;
            if (yy < 0 || yy >= HH) continue;
#pragma unroll
            for (int kw = 0; kw < 3; kw++) {
                int xx = x + kw - 1;
                if (xx < 0 || xx >= WW) continue;
                size_t idx = ((size_t)((b*8 + tt)*HH + yy) * WW + xx) * MFF + m;
                acc += in[idx] * w[((kd*3 + kh)*3 + kw) * MFF + m];
            }
        }
    }
    // exact gelu: 0.5*x*(1+erf(x/sqrt(2)))
    out[e] = 0.5f * acc * (1.0f + erff(acc * 0.7071067811865475f));
}

// ---------------- host launcher ----------------
extern "C" void kernel_launch(void* const* d_in, const int* in_sizes, int n_in,
                              void* d_out, int out_size)
{
    const float* x      = (const float*)d_in[0];
    const float* ln1_g  = (const float*)d_in[1];
    const float* ln1_b  = (const float*)d_in[2];
    const float* qkv_w  = (const float*)d_in[3];
    const float* qkv_b  = (const float*)d_in[4];
    const float* rpb    = (const float*)d_in[5];
    const float* proj_w = (const float*)d_in[6];
    const float* proj_b = (const float*)d_in[7];
    const float* ln2_g  = (const float*)d_in[8];
    const float* ln2_b  = (const float*)d_in[9];
    const float* fc1_w  = (const float*)d_in[10];
    const float* fc1_b  = (const float*)d_in[11];
    const float* dw_w   = (const float*)d_in[12];
    const float* dw_b   = (const float*)d_in[13];
    const float* fc2_w  = (const float*)d_in[14];
    const float* fc2_b  = (const float*)d_in[15];
    const float* out_g  = (const float*)d_in[16];
    const float* out_b  = (const float*)d_in[17];
    float* out = (float*)d_out;

    static float *p_h=nullptr,*p_ln,*p_qkv,*p_att,*p_f1,*p_f2;
    if (!p_h) {
        cudaGetSymbolAddress((void**)&p_h,   g_h);
        cudaGetSymbolAddress((void**)&p_ln,  g_ln);
        cudaGetSymbolAddress((void**)&p_qkv, g_qkv);
        cudaGetSymbolAddress((void**)&p_att, g_att);
        cudaGetSymbolAddress((void**)&p_f1,  g_f1);
        cudaGetSymbolAddress((void**)&p_f2,  g_f2);
        cudaFuncSetAttribute(k_attn3, cudaFuncAttributeMaxDynamicSharedMemorySize,
                             ATTN3_SMEM);
    }

    dim3 tposeGrid(SPA/32, CC/32, 2);
    dim3 tposeBlk(32, 8);
    dim3 attnGrid(WW/8, HH/8, BT*2);   // 5 x 5 x 32 (z packs frame + head-pair)

    k_transpose_in<<<tposeGrid, tposeBlk>>>(x, p_h);

    for (int l = 0; l < 2; l++) {
        // --- attention sub-block ---
        k_layernorm<<<NTOK, 128>>>(p_h, ln1_g + l*CC, ln1_b + l*CC, p_ln);
        // qkv: [25600,128] @ [128,384]
        k_tgemm<false><<<dim3(384/128, NTOK/128), 256>>>(
            p_ln, qkv_w + (size_t)l*CC*384, qkv_b + l*384, nullptr, p_qkv,
            NTOK, 384, CC);
        k_attn3<<<attnGrid, 128, ATTN3_SMEM>>>(p_qkv, rpb + l*HEADS*13*13, p_att);
        // proj: [25600,128] @ [128,128] + residual
        k_tgemm<true><<<dim3(CC/128, NTOK/128), 256>>>(
            p_att, proj_w + (size_t)l*CC*CC, proj_b + l*CC, p_h, p_h,
            NTOK, CC, CC);

        // --- mixffn sub-block ---
        k_layernorm<<<NTOK, 128>>>(p_h, ln2_g + l*CC, ln2_b + l*CC, p_ln);
        // fc1: [25600,128] @ [128,512]
        k_tgemm<false><<<dim3(MFF/128, NTOK/128), 256>>>(
            p_ln, fc1_w + (size_t)l*CC*MFF, fc1_b + l*MFF, nullptr, p_f1,
            NTOK, MFF, CC);
        k_dwconv_gelu<<<(NTOK*MFF + 255)/256, 256>>>(
            p_f1, dw_w + (size_t)l*27*MFF, dw_b + l*MFF, p_f2);
        // fc2: [25600,512] @ [512,128] + residual
        k_tgemm<true><<<dim3(CC/128, NTOK/128), 256>>>(
            p_f2, fc2_w + (size_t)l*MFF*CC, fc2_b + l*CC, p_h, p_h,
            NTOK, CC, MFF);
    }

    k_layernorm<<<NTOK, 128>>>(p_h, out_g, out_b, p_ln);
    k_transpose_out<<<tposeGrid, tposeBlk>>>(p_ln, out);
}